// round 4
// baseline (speedup 1.0000x reference)
#include <cuda_runtime.h>

#define NMAX 100000
#define EMAX 3200000

// scratch (all __device__ globals; no allocation anywhere)
__device__ int    g_degi  [NMAX];
__device__ int    g_rowptr[NMAX + 1];
__device__ int    g_next  [NMAX];
__device__ int    g_ssrc  [EMAX];     // src ids sorted by dst (CSR adjacency)
__device__ float  g_dis   [NMAX];
__device__ float4 g_y     [NMAX * 4]; // dis * x1hat  (layer-1 message)
__device__ float4 g_y2    [NMAX * 4]; // dis * x2hat  (layer-2 message)
__device__ float4 g_A1    [NMAX * 4]; // x1hat @ w_e1[0:16]
__device__ float4 g_B1    [NMAX * 4]; // x1hat @ w_e1[19:35]
__device__ float4 g_A2    [NMAX * 4]; // x2hat @ w_e2[0:16]
__device__ float4 g_B2    [NMAX * 4]; // x2hat @ w_e2[32:48]

__device__ __forceinline__ float relu(float v) { return fmaxf(v, 0.0f); }

// ---------------------------------------------------------------- degree
__global__ void k_deg(const int* __restrict__ ei, int E) {
    int e = blockIdx.x * blockDim.x + threadIdx.x;
    if (e < E) atomicAdd(&g_degi[ei[(size_t)E + e]], 1);
}

// ------------------------------------------ exclusive scan (single block)
__global__ void k_scan(int N, int E) {
    __shared__ int ssum[1024];
    int t = threadIdx.x;
    int CH = (N + 1023) >> 10;
    int base = t * CH;
    int end  = min(base + CH, N);
    int s = 0;
    for (int i = base; i < end; i++) s += g_degi[i];
    ssum[t] = s;
    __syncthreads();
    for (int off = 1; off < 1024; off <<= 1) {
        int u = (t >= off) ? ssum[t - off] : 0;
        __syncthreads();
        ssum[t] += u;
        __syncthreads();
    }
    int running = ssum[t] - s;
    for (int i = base; i < end; i++) {
        g_rowptr[i] = running;
        g_next[i]   = running;
        running += g_degi[i];
    }
    if (t == 0) g_rowptr[N] = E;
}

// ----------------------------------------------------- scatter into CSR
__global__ void k_scatter(const int* __restrict__ ei, int E) {
    int e = blockIdx.x * blockDim.x + threadIdx.x;
    if (e >= E) return;
    int src = ei[e];
    int dst = ei[(size_t)E + e];
    int pos = atomicAdd(&g_next[dst], 1);
    g_ssrc[pos] = src;
}

// ------------------------------------------------- node precompute layer 1
__global__ void k_node1(const float* __restrict__ x,
                        const float* __restrict__ wn1, const float* __restrict__ bn1,
                        const float* __restrict__ we1, int N) {
    __shared__ float swn[48], sbn[16], sA[256], sB[256];
    for (int i = threadIdx.x; i < 48; i += blockDim.x) swn[i] = wn1[i];
    for (int i = threadIdx.x; i < 16; i += blockDim.x) sbn[i] = bn1[i];
    for (int i = threadIdx.x; i < 256; i += blockDim.x) {
        sA[i] = we1[i];            // rows 0..15  (x_src part)
        sB[i] = we1[304 + i];      // rows 19..34 (x_dst part)
    }
    __syncthreads();
    int n = blockIdx.x * blockDim.x + threadIdx.x;
    if (n >= N) return;

    float x0 = x[(size_t)n*3], x1 = x[(size_t)n*3+1], x2 = x[(size_t)n*3+2];
    float dis = rsqrtf((float)g_degi[n]);
    g_dis[n] = dis;

    float h[16];
#pragma unroll
    for (int k = 0; k < 16; k++)
        h[k] = sbn[k] + x0*swn[k] + x1*swn[16+k] + x2*swn[32+k];

    float4* Y = &g_y[(size_t)n*4];
#pragma unroll
    for (int q = 0; q < 4; q++)
        Y[q] = make_float4(dis*h[4*q], dis*h[4*q+1], dis*h[4*q+2], dis*h[4*q+3]);

    float a[16], b[16];
#pragma unroll
    for (int k = 0; k < 16; k++) { a[k] = 0.f; b[k] = 0.f; }
#pragma unroll
    for (int j = 0; j < 16; j++)
#pragma unroll
        for (int k = 0; k < 16; k++) {
            a[k] += h[j] * sA[j*16+k];
            b[k] += h[j] * sB[j*16+k];
        }
    float4* A = &g_A1[(size_t)n*4];
    float4* B = &g_B1[(size_t)n*4];
#pragma unroll
    for (int q = 0; q < 4; q++) {
        A[q] = make_float4(a[4*q], a[4*q+1], a[4*q+2], a[4*q+3]);
        B[q] = make_float4(b[4*q], b[4*q+1], b[4*q+2], b[4*q+3]);
    }
}

// ---------- fused: quad CSR-gather aggregation (layer1) + node2 transform
// block = 256 threads = 64 nodes (quad per node in phase 1)
__global__ void k_agg_node2(const float* __restrict__ wn2, const float* __restrict__ bn2,
                            const float* __restrict__ we2, int N) {
    __shared__ float sw[256], sbn[16], sA[256], sB[256];
    __shared__ float sagg[64 * 17];
    for (int i = threadIdx.x; i < 16; i += blockDim.x) sbn[i] = bn2[i];
    for (int i = threadIdx.x; i < 256; i += blockDim.x) {
        sw[i] = wn2[i];
        sA[i] = we2[i];            // rows 0..15
        sB[i] = we2[512 + i];      // rows 32..47
    }
    __syncthreads();

    int t = threadIdx.x;
    int lane = t & 3, q = t >> 2;
    int n = blockIdx.x * 64 + q;

    float4 acc = make_float4(0.f, 0.f, 0.f, 0.f);
    if (n < N) {
        int s  = g_rowptr[n];
        int en = g_rowptr[n + 1];
#pragma unroll 4
        for (int p = s; p < en; p++) {
            int src = g_ssrc[p];
            float4 v = g_y[(size_t)src * 4 + lane];
            acc.x += v.x; acc.y += v.y; acc.z += v.z; acc.w += v.w;
        }
    }
    float* sg = &sagg[q * 17 + lane * 4];
    sg[0] = acc.x; sg[1] = acc.y; sg[2] = acc.z; sg[3] = acc.w;
    __syncthreads();

    // phase 2: one thread per node
    if (t >= 64) return;
    int n2 = blockIdx.x * 64 + t;
    if (n2 >= N) return;

    float dis = g_dis[n2];
    const float* ag = &sagg[t * 17];
    float h[16];
#pragma unroll
    for (int k = 0; k < 16; k++) h[k] = relu(dis * ag[k]);

    float v[16];
#pragma unroll
    for (int k = 0; k < 16; k++) v[k] = sbn[k];
#pragma unroll
    for (int j = 0; j < 16; j++)
#pragma unroll
        for (int k = 0; k < 16; k++) v[k] += h[j] * sw[j*16+k];

    float4* Y = &g_y2[(size_t)n2*4];
#pragma unroll
    for (int qq = 0; qq < 4; qq++)
        Y[qq] = make_float4(dis*v[4*qq], dis*v[4*qq+1], dis*v[4*qq+2], dis*v[4*qq+3]);

    float a[16], b[16];
#pragma unroll
    for (int k = 0; k < 16; k++) { a[k] = 0.f; b[k] = 0.f; }
#pragma unroll
    for (int j = 0; j < 16; j++)
#pragma unroll
        for (int k = 0; k < 16; k++) {
            a[k] += v[j] * sA[j*16+k];
            b[k] += v[j] * sB[j*16+k];
        }
    float4* A = &g_A2[(size_t)n2*4];
    float4* B = &g_B2[(size_t)n2*4];
#pragma unroll
    for (int qq = 0; qq < 4; qq++) {
        A[qq] = make_float4(a[4*qq], a[4*qq+1], a[4*qq+2], a[4*qq+3]);
        B[qq] = make_float4(b[4*qq], b[4*qq+1], b[4*qq+2], b[4*qq+3]);
    }
}

// ---------- fused: quad CSR-gather aggregation (layer2) + node output MLP
__global__ void k_agg_node3(const float* __restrict__ wnn1, const float* __restrict__ bnn1,
                            const float* __restrict__ wnn2, const float* __restrict__ bnn2,
                            float* __restrict__ out_node, int N) {
    __shared__ float sw1[256], sb1[16], sw2[48], sb2[3];
    __shared__ float sagg[64 * 17];
    for (int i = threadIdx.x; i < 256; i += blockDim.x) sw1[i] = wnn1[i];
    for (int i = threadIdx.x; i < 48;  i += blockDim.x) sw2[i] = wnn2[i];
    for (int i = threadIdx.x; i < 16;  i += blockDim.x) sb1[i] = bnn1[i];
    if (threadIdx.x < 3) sb2[threadIdx.x] = bnn2[threadIdx.x];
    __syncthreads();

    int t = threadIdx.x;
    int lane = t & 3, q = t >> 2;
    int n = blockIdx.x * 64 + q;

    float4 acc = make_float4(0.f, 0.f, 0.f, 0.f);
    if (n < N) {
        int s  = g_rowptr[n];
        int en = g_rowptr[n + 1];
#pragma unroll 4
        for (int p = s; p < en; p++) {
            int src = g_ssrc[p];
            float4 v = g_y2[(size_t)src * 4 + lane];
            acc.x += v.x; acc.y += v.y; acc.z += v.z; acc.w += v.w;
        }
    }
    float* sg = &sagg[q * 17 + lane * 4];
    sg[0] = acc.x; sg[1] = acc.y; sg[2] = acc.z; sg[3] = acc.w;
    __syncthreads();

    if (t >= 64) return;
    int n2 = blockIdx.x * 64 + t;
    if (n2 >= N) return;

    float dis = g_dis[n2];
    const float* ag = &sagg[t * 17];
    float h[16];
#pragma unroll
    for (int k = 0; k < 16; k++) h[k] = relu(dis * ag[k]);

    float tv[16];
#pragma unroll
    for (int k = 0; k < 16; k++) tv[k] = sb1[k];
#pragma unroll
    for (int j = 0; j < 16; j++)
#pragma unroll
        for (int k = 0; k < 16; k++) tv[k] += h[j] * sw1[j*16+k];

    float o0 = sb2[0], o1 = sb2[1], o2 = sb2[2];
#pragma unroll
    for (int j = 0; j < 16; j++) {
        float tj = relu(tv[j]);
        o0 += tj * sw2[j*3    ];
        o1 += tj * sw2[j*3 + 1];
        o2 += tj * sw2[j*3 + 2];
    }
    out_node[(size_t)n2*3    ] = o0;
    out_node[(size_t)n2*3 + 1] = o1;
    out_node[(size_t)n2*3 + 2] = o2;
}

// ------- layer-2 edge kernel, QUAD PER EDGE (coalesced 64B gathers)
// lane l owns channels 4l..4l+3; cross-lane via width-4 shuffles.
__global__ void k_edge2q(const int* __restrict__ ei, const float* __restrict__ ea,
                         const float* __restrict__ we1, const float* __restrict__ be1,
                         const float* __restrict__ we2, const float* __restrict__ be2,
                         const float* __restrict__ wen1, const float* __restrict__ ben1,
                         const float* __restrict__ wen2, const float* __restrict__ ben2,
                         float* __restrict__ out_edge, int E) {
    __shared__ float sm1[48], sbe1[16], sm2[256], sbe2[16], sw1[256], sb1[16], sw2[48], sb2[3];
    for (int i = threadIdx.x; i < 48; i += blockDim.x) {
        sm1[i] = we1[256 + i];     // w_e1 rows 16..18 (edge_attr part)
        sw2[i] = wen2[i];
    }
    for (int i = threadIdx.x; i < 256; i += blockDim.x) {
        sm2[i] = we2[256 + i];     // w_e2 rows 16..31 (edge part)
        sw1[i] = wen1[i];
    }
    for (int i = threadIdx.x; i < 16; i += blockDim.x) {
        sbe1[i] = be1[i]; sbe2[i] = be2[i]; sb1[i] = ben1[i];
    }
    if (threadIdx.x < 3) sb2[threadIdx.x] = ben2[threadIdx.x];
    __syncthreads();

    int t = threadIdx.x;
    int lane = t & 3, q = t >> 2;
    int eidx = blockIdx.x * 64 + q;
    bool valid = (eidx < E);
    int e = valid ? eidx : (E - 1);   // clamp: keep all lanes active for shuffles

    int src = ei[e];
    int dst = ei[(size_t)E + e];
    int kb = lane * 4;   // channel base for this lane

    float4 a1 = g_A1[(size_t)src*4 + lane];
    float4 b1 = g_B1[(size_t)dst*4 + lane];
    float4 a2 = g_A2[(size_t)src*4 + lane];
    float4 b2 = g_B2[(size_t)dst*4 + lane];
    float ea0 = ea[(size_t)e*3], ea1 = ea[(size_t)e*3+1], ea2 = ea[(size_t)e*3+2];

    // e1 (4 channels per lane)
    float e1v[4];
    {
        float av[4] = {a1.x, a1.y, a1.z, a1.w};
        float bv[4] = {b1.x, b1.y, b1.z, b1.w};
#pragma unroll
        for (int i = 0; i < 4; i++) {
            int k = kb + i;
            e1v[i] = relu(av[i] + bv[i] + sbe1[k]
                          + ea0*sm1[k] + ea1*sm1[16+k] + ea2*sm1[32+k]);
        }
    }

    // e2 = relu(A2 + B2 + be2 + e1 @ sm2)
    float e2v[4] = { a2.x + b2.x + sbe2[kb  ],
                     a2.y + b2.y + sbe2[kb+1],
                     a2.z + b2.z + sbe2[kb+2],
                     a2.w + b2.w + sbe2[kb+3] };
#pragma unroll
    for (int j = 0; j < 16; j++) {
        float ej = __shfl_sync(0xFFFFFFFFu, e1v[j & 3], j >> 2, 4);
#pragma unroll
        for (int i = 0; i < 4; i++)
            e2v[i] += ej * sm2[j*16 + kb + i];
    }
#pragma unroll
    for (int i = 0; i < 4; i++) e2v[i] = relu(e2v[i]);

    // t = e2 @ wen1 + b
    float tv[4] = { sb1[kb], sb1[kb+1], sb1[kb+2], sb1[kb+3] };
#pragma unroll
    for (int j = 0; j < 16; j++) {
        float ej = __shfl_sync(0xFFFFFFFFu, e2v[j & 3], j >> 2, 4);
#pragma unroll
        for (int i = 0; i < 4; i++)
            tv[i] += ej * sw1[j*16 + kb + i];
    }

    // o = relu(t) @ wen2 + b  (partial per lane, then quad reduce)
    float o0 = 0.f, o1 = 0.f, o2 = 0.f;
#pragma unroll
    for (int i = 0; i < 4; i++) {
        float tj = relu(tv[i]);
        int j = kb + i;
        o0 += tj * sw2[j*3    ];
        o1 += tj * sw2[j*3 + 1];
        o2 += tj * sw2[j*3 + 2];
    }
    o0 += __shfl_xor_sync(0xFFFFFFFFu, o0, 1, 4);
    o0 += __shfl_xor_sync(0xFFFFFFFFu, o0, 2, 4);
    o1 += __shfl_xor_sync(0xFFFFFFFFu, o1, 1, 4);
    o1 += __shfl_xor_sync(0xFFFFFFFFu, o1, 2, 4);
    o2 += __shfl_xor_sync(0xFFFFFFFFu, o2, 1, 4);
    o2 += __shfl_xor_sync(0xFFFFFFFFu, o2, 2, 4);

    if (valid && lane < 3) {
        float val = (lane == 0) ? (o0 + sb2[0]) : (lane == 1) ? (o1 + sb2[1]) : (o2 + sb2[2]);
        out_edge[(size_t)e*3 + lane] = val;
    }
}

extern "C" void kernel_launch(void* const* d_in, const int* in_sizes, int n_in,
                              void* d_out, int out_size) {
    const float* x    = (const float*)d_in[0];
    const float* ea   = (const float*)d_in[1];
    const int*   ei   = (const int*)d_in[2];      // int32 (JAX x64 disabled)
    const float *wn1 = (const float*)d_in[3],  *bn1 = (const float*)d_in[4];
    const float *we1 = (const float*)d_in[5],  *be1 = (const float*)d_in[6];
    const float *wn2 = (const float*)d_in[7],  *bn2 = (const float*)d_in[8];
    const float *we2 = (const float*)d_in[9],  *be2 = (const float*)d_in[10];
    const float *wnn1= (const float*)d_in[11], *bnn1= (const float*)d_in[12];
    const float *wnn2= (const float*)d_in[13], *bnn2= (const float*)d_in[14];
    const float *wen1= (const float*)d_in[15], *ben1= (const float*)d_in[16];
    const float *wen2= (const float*)d_in[17], *ben2= (const float*)d_in[18];

    int N = in_sizes[0] / 3;
    int E = in_sizes[1] / 3;
    float* out_node = (float*)d_out;
    float* out_edge = out_node + (size_t)N * 3;

    void* pdegi;
    cudaGetSymbolAddress(&pdegi, g_degi);
    cudaMemsetAsync(pdegi, 0, (size_t)N * sizeof(int));

    const int TB = 256;
    int gbE  = (E + TB - 1) / TB;
    int gbN  = (N + TB - 1) / TB;
    int gbN64 = (N + 63) / 64;     // fused agg kernels: 64 nodes/block
    int gbE64 = (E + 63) / 64;     // quad edge kernel: 64 edges/block

    k_deg     <<<gbE,   TB>>>(ei, E);
    k_scan    <<<1,   1024>>>(N, E);
    k_scatter <<<gbE,   TB>>>(ei, E);
    k_node1   <<<gbN,   TB>>>(x, wn1, bn1, we1, N);
    k_agg_node2<<<gbN64, TB>>>(wn2, bn2, we2, N);
    k_edge2q  <<<gbE64, TB>>>(ei, ea, we1, be1, we2, be2, wen1, ben1, wen2, ben2,
                              out_edge, E);
    k_agg_node3<<<gbN64, TB>>>(wnn1, bnn1, wnn2, bnn2, out_node, N);
}

// round 5
// speedup vs baseline: 1.5430x; 1.5430x over previous
#include <cuda_runtime.h>

#define NMAX 100000
#define EMAX 3200000

// scratch (all __device__ globals; no allocation anywhere)
__device__ int    g_degi  [NMAX];
__device__ int    g_rowptr[NMAX + 1];
__device__ int    g_next  [NMAX];
__device__ int    g_bsum  [128];
__device__ int    g_boff  [128];
__device__ int    g_ssrc  [EMAX];     // src ids sorted by dst (CSR adjacency)
__device__ float  g_dis   [NMAX];
__device__ float4 g_y     [NMAX * 4]; // dis * x1hat  (layer-1 message)
__device__ float4 g_y2    [NMAX * 4]; // dis * x2hat  (layer-2 message)
__device__ float4 g_A1    [NMAX * 4];
__device__ float4 g_B1    [NMAX * 4];
__device__ float4 g_A2    [NMAX * 4];
__device__ float4 g_B2    [NMAX * 4];

__device__ __forceinline__ float relu(float v) { return fmaxf(v, 0.0f); }

// ---------------------------------------------------------------- degree
__global__ void k_deg(const int* __restrict__ ei, int E) {
    int e = blockIdx.x * blockDim.x + threadIdx.x;
    if (e < E) atomicAdd(&g_degi[ei[(size_t)E + e]], 1);
}

// ------------------------------------- two-level scan, fully coalesced
__global__ void k_bsum(int N) {              // grid = NB, block = 1024
    int i = blockIdx.x * 1024 + threadIdx.x;
    int v = (i < N) ? g_degi[i] : 0;
#pragma unroll
    for (int o = 16; o; o >>= 1) v += __shfl_down_sync(0xFFFFFFFFu, v, o);
    __shared__ int ws[32];
    if ((threadIdx.x & 31) == 0) ws[threadIdx.x >> 5] = v;
    __syncthreads();
    if (threadIdx.x < 32) {
        int u = ws[threadIdx.x];
#pragma unroll
        for (int o = 16; o; o >>= 1) u += __shfl_down_sync(0xFFFFFFFFu, u, o);
        if (threadIdx.x == 0) g_bsum[blockIdx.x] = u;
    }
}

__global__ void k_bscan(int NB, int N, int E) {   // 1 block, 1 thread does work
    if (threadIdx.x == 0) {
        int run = 0;
        for (int b = 0; b < NB; b++) { g_boff[b] = run; run += g_bsum[b]; }
        g_rowptr[N] = E;
    }
}

__global__ void k_rowptr(int N) {            // grid = NB, block = 1024
    __shared__ int s[1024];
    int i = blockIdx.x * 1024 + threadIdx.x;
    int d = (i < N) ? g_degi[i] : 0;
    s[threadIdx.x] = d;
    __syncthreads();
    for (int off = 1; off < 1024; off <<= 1) {
        int u = (threadIdx.x >= off) ? s[threadIdx.x - off] : 0;
        __syncthreads();
        s[threadIdx.x] += u;
        __syncthreads();
    }
    if (i < N) {
        int excl = g_boff[blockIdx.x] + s[threadIdx.x] - d;
        g_rowptr[i] = excl;
        g_next[i]   = excl;
    }
}

// ----------------------------------------------------- scatter into CSR
__global__ void k_scatter(const int* __restrict__ ei, int E) {
    int e = blockIdx.x * blockDim.x + threadIdx.x;
    if (e >= E) return;
    int src = ei[e];
    int dst = ei[(size_t)E + e];
    int pos = atomicAdd(&g_next[dst], 1);
    g_ssrc[pos] = src;
}

// ------------------------------------------------- node precompute layer 1
__global__ void k_node1(const float* __restrict__ x,
                        const float* __restrict__ wn1, const float* __restrict__ bn1,
                        const float* __restrict__ we1, int N) {
    __shared__ float swn[48], sbn[16], sA[256], sB[256];
    for (int i = threadIdx.x; i < 48; i += blockDim.x) swn[i] = wn1[i];
    for (int i = threadIdx.x; i < 16; i += blockDim.x) sbn[i] = bn1[i];
    for (int i = threadIdx.x; i < 256; i += blockDim.x) {
        sA[i] = we1[i];            // rows 0..15  (x_src part)
        sB[i] = we1[304 + i];      // rows 19..34 (x_dst part)
    }
    __syncthreads();
    int n = blockIdx.x * blockDim.x + threadIdx.x;
    if (n >= N) return;

    float x0 = x[(size_t)n*3], x1 = x[(size_t)n*3+1], x2 = x[(size_t)n*3+2];
    float dis = rsqrtf((float)g_degi[n]);
    g_dis[n] = dis;

    float h[16];
#pragma unroll
    for (int k = 0; k < 16; k++)
        h[k] = sbn[k] + x0*swn[k] + x1*swn[16+k] + x2*swn[32+k];

    float4* Y = &g_y[(size_t)n*4];
#pragma unroll
    for (int q = 0; q < 4; q++)
        Y[q] = make_float4(dis*h[4*q], dis*h[4*q+1], dis*h[4*q+2], dis*h[4*q+3]);

    float a[16], b[16];
#pragma unroll
    for (int k = 0; k < 16; k++) { a[k] = 0.f; b[k] = 0.f; }
#pragma unroll
    for (int j = 0; j < 16; j++)
#pragma unroll
        for (int k = 0; k < 16; k++) {
            a[k] += h[j] * sA[j*16+k];
            b[k] += h[j] * sB[j*16+k];
        }
    float4* A = &g_A1[(size_t)n*4];
    float4* B = &g_B1[(size_t)n*4];
#pragma unroll
    for (int q = 0; q < 4; q++) {
        A[q] = make_float4(a[4*q], a[4*q+1], a[4*q+2], a[4*q+3]);
        B[q] = make_float4(b[4*q], b[4*q+1], b[4*q+2], b[4*q+3]);
    }
}

// ---------- fused: quad CSR-gather aggregation (layer1) + node2 transform
__global__ void k_agg_node2(const float* __restrict__ wn2, const float* __restrict__ bn2,
                            const float* __restrict__ we2, int N) {
    __shared__ float sw[256], sbn[16], sA[256], sB[256];
    __shared__ float sagg[64 * 17];
    for (int i = threadIdx.x; i < 16; i += blockDim.x) sbn[i] = bn2[i];
    for (int i = threadIdx.x; i < 256; i += blockDim.x) {
        sw[i] = wn2[i];
        sA[i] = we2[i];
        sB[i] = we2[512 + i];
    }
    __syncthreads();

    int t = threadIdx.x;
    int lane = t & 3, q = t >> 2;
    int n = blockIdx.x * 64 + q;

    float4 acc = make_float4(0.f, 0.f, 0.f, 0.f);
    if (n < N) {
        int s  = g_rowptr[n];
        int en = g_rowptr[n + 1];
#pragma unroll 4
        for (int p = s; p < en; p++) {
            int src = g_ssrc[p];
            float4 v = g_y[(size_t)src * 4 + lane];
            acc.x += v.x; acc.y += v.y; acc.z += v.z; acc.w += v.w;
        }
    }
    float* sg = &sagg[q * 17 + lane * 4];
    sg[0] = acc.x; sg[1] = acc.y; sg[2] = acc.z; sg[3] = acc.w;
    __syncthreads();

    if (t >= 64) return;
    int n2 = blockIdx.x * 64 + t;
    if (n2 >= N) return;

    float dis = g_dis[n2];
    const float* ag = &sagg[t * 17];
    float h[16];
#pragma unroll
    for (int k = 0; k < 16; k++) h[k] = relu(dis * ag[k]);

    float v[16];
#pragma unroll
    for (int k = 0; k < 16; k++) v[k] = sbn[k];
#pragma unroll
    for (int j = 0; j < 16; j++)
#pragma unroll
        for (int k = 0; k < 16; k++) v[k] += h[j] * sw[j*16+k];

    float4* Y = &g_y2[(size_t)n2*4];
#pragma unroll
    for (int qq = 0; qq < 4; qq++)
        Y[qq] = make_float4(dis*v[4*qq], dis*v[4*qq+1], dis*v[4*qq+2], dis*v[4*qq+3]);

    float a[16], b[16];
#pragma unroll
    for (int k = 0; k < 16; k++) { a[k] = 0.f; b[k] = 0.f; }
#pragma unroll
    for (int j = 0; j < 16; j++)
#pragma unroll
        for (int k = 0; k < 16; k++) {
            a[k] += v[j] * sA[j*16+k];
            b[k] += v[j] * sB[j*16+k];
        }
    float4* A = &g_A2[(size_t)n2*4];
    float4* B = &g_B2[(size_t)n2*4];
#pragma unroll
    for (int qq = 0; qq < 4; qq++) {
        A[qq] = make_float4(a[4*qq], a[4*qq+1], a[4*qq+2], a[4*qq+3]);
        B[qq] = make_float4(b[4*qq], b[4*qq+1], b[4*qq+2], b[4*qq+3]);
    }
}

// ---------- fused: quad CSR-gather aggregation (layer2) + node output MLP
__global__ void k_agg_node3(const float* __restrict__ wnn1, const float* __restrict__ bnn1,
                            const float* __restrict__ wnn2, const float* __restrict__ bnn2,
                            float* __restrict__ out_node, int N) {
    __shared__ float sw1[256], sb1[16], sw2[48], sb2[3];
    __shared__ float sagg[64 * 17];
    for (int i = threadIdx.x; i < 256; i += blockDim.x) sw1[i] = wnn1[i];
    for (int i = threadIdx.x; i < 48;  i += blockDim.x) sw2[i] = wnn2[i];
    for (int i = threadIdx.x; i < 16;  i += blockDim.x) sb1[i] = bnn1[i];
    if (threadIdx.x < 3) sb2[threadIdx.x] = bnn2[threadIdx.x];
    __syncthreads();

    int t = threadIdx.x;
    int lane = t & 3, q = t >> 2;
    int n = blockIdx.x * 64 + q;

    float4 acc = make_float4(0.f, 0.f, 0.f, 0.f);
    if (n < N) {
        int s  = g_rowptr[n];
        int en = g_rowptr[n + 1];
#pragma unroll 4
        for (int p = s; p < en; p++) {
            int src = g_ssrc[p];
            float4 v = g_y2[(size_t)src * 4 + lane];
            acc.x += v.x; acc.y += v.y; acc.z += v.z; acc.w += v.w;
        }
    }
    float* sg = &sagg[q * 17 + lane * 4];
    sg[0] = acc.x; sg[1] = acc.y; sg[2] = acc.z; sg[3] = acc.w;
    __syncthreads();

    if (t >= 64) return;
    int n2 = blockIdx.x * 64 + t;
    if (n2 >= N) return;

    float dis = g_dis[n2];
    const float* ag = &sagg[t * 17];
    float h[16];
#pragma unroll
    for (int k = 0; k < 16; k++) h[k] = relu(dis * ag[k]);

    float tv[16];
#pragma unroll
    for (int k = 0; k < 16; k++) tv[k] = sb1[k];
#pragma unroll
    for (int j = 0; j < 16; j++)
#pragma unroll
        for (int k = 0; k < 16; k++) tv[k] += h[j] * sw1[j*16+k];

    float o0 = sb2[0], o1 = sb2[1], o2 = sb2[2];
#pragma unroll
    for (int j = 0; j < 16; j++) {
        float tj = relu(tv[j]);
        o0 += tj * sw2[j*3    ];
        o1 += tj * sw2[j*3 + 1];
        o2 += tj * sw2[j*3 + 2];
    }
    out_node[(size_t)n2*3    ] = o0;
    out_node[(size_t)n2*3 + 1] = o1;
    out_node[(size_t)n2*3 + 2] = o2;
}

// ------- layer-2 edge kernel (scalar, one thread per edge)
__global__ void k_edge2(const int* __restrict__ ei, const float* __restrict__ ea,
                        const float* __restrict__ we1, const float* __restrict__ be1,
                        const float* __restrict__ we2, const float* __restrict__ be2,
                        const float* __restrict__ wen1, const float* __restrict__ ben1,
                        const float* __restrict__ wen2, const float* __restrict__ ben2,
                        float* __restrict__ out_edge, int E) {
    __shared__ float sm1[48], sbe1[16], sm2[256], sbe2[16], sw1[256], sb1[16], sw2[48], sb2[3];
    for (int i = threadIdx.x; i < 48; i += blockDim.x) {
        sm1[i] = we1[256 + i];
        sw2[i] = wen2[i];
    }
    for (int i = threadIdx.x; i < 256; i += blockDim.x) {
        sm2[i] = we2[256 + i];
        sw1[i] = wen1[i];
    }
    for (int i = threadIdx.x; i < 16; i += blockDim.x) {
        sbe1[i] = be1[i]; sbe2[i] = be2[i]; sb1[i] = ben1[i];
    }
    if (threadIdx.x < 3) sb2[threadIdx.x] = ben2[threadIdx.x];
    __syncthreads();

    int e = blockIdx.x * blockDim.x + threadIdx.x;
    if (e >= E) return;
    int src = ei[e];
    int dst = ei[(size_t)E + e];

    float ea0 = ea[(size_t)e*3], ea1 = ea[(size_t)e*3+1], ea2 = ea[(size_t)e*3+2];
    float e1v[16];
    {
        const float4* A = &g_A1[(size_t)src*4];
        const float4* B = &g_B1[(size_t)dst*4];
        float av[16], bv[16];
#pragma unroll
        for (int q = 0; q < 4; q++) {
            float4 ta = A[q], tb = B[q];
            av[4*q]=ta.x; av[4*q+1]=ta.y; av[4*q+2]=ta.z; av[4*q+3]=ta.w;
            bv[4*q]=tb.x; bv[4*q+1]=tb.y; bv[4*q+2]=tb.z; bv[4*q+3]=tb.w;
        }
#pragma unroll
        for (int k = 0; k < 16; k++)
            e1v[k] = relu(av[k] + bv[k] + sbe1[k]
                          + ea0*sm1[k] + ea1*sm1[16+k] + ea2*sm1[32+k]);
    }

    float e2v[16];
    {
        const float4* A = &g_A2[(size_t)src*4];
        const float4* B = &g_B2[(size_t)dst*4];
#pragma unroll
        for (int q = 0; q < 4; q++) {
            float4 ta = A[q], tb = B[q];
            e2v[4*q  ] = ta.x + tb.x + sbe2[4*q  ];
            e2v[4*q+1] = ta.y + tb.y + sbe2[4*q+1];
            e2v[4*q+2] = ta.z + tb.z + sbe2[4*q+2];
            e2v[4*q+3] = ta.w + tb.w + sbe2[4*q+3];
        }
#pragma unroll
        for (int j = 0; j < 16; j++)
#pragma unroll
            for (int k = 0; k < 16; k++)
                e2v[k] += e1v[j] * sm2[j*16+k];
#pragma unroll
        for (int k = 0; k < 16; k++) e2v[k] = relu(e2v[k]);
    }

    float t[16];
#pragma unroll
    for (int k = 0; k < 16; k++) t[k] = sb1[k];
#pragma unroll
    for (int j = 0; j < 16; j++)
#pragma unroll
        for (int k = 0; k < 16; k++) t[k] += e2v[j] * sw1[j*16+k];
    float o0 = sb2[0], o1 = sb2[1], o2 = sb2[2];
#pragma unroll
    for (int j = 0; j < 16; j++) {
        float tj = relu(t[j]);
        o0 += tj * sw2[j*3    ];
        o1 += tj * sw2[j*3 + 1];
        o2 += tj * sw2[j*3 + 2];
    }
    out_edge[(size_t)e*3    ] = o0;
    out_edge[(size_t)e*3 + 1] = o1;
    out_edge[(size_t)e*3 + 2] = o2;
}

extern "C" void kernel_launch(void* const* d_in, const int* in_sizes, int n_in,
                              void* d_out, int out_size) {
    const float* x    = (const float*)d_in[0];
    const float* ea   = (const float*)d_in[1];
    const int*   ei   = (const int*)d_in[2];      // int32 (JAX x64 disabled)
    const float *wn1 = (const float*)d_in[3],  *bn1 = (const float*)d_in[4];
    const float *we1 = (const float*)d_in[5],  *be1 = (const float*)d_in[6];
    const float *wn2 = (const float*)d_in[7],  *bn2 = (const float*)d_in[8];
    const float *we2 = (const float*)d_in[9],  *be2 = (const float*)d_in[10];
    const float *wnn1= (const float*)d_in[11], *bnn1= (const float*)d_in[12];
    const float *wnn2= (const float*)d_in[13], *bnn2= (const float*)d_in[14];
    const float *wen1= (const float*)d_in[15], *ben1= (const float*)d_in[16];
    const float *wen2= (const float*)d_in[17], *ben2= (const float*)d_in[18];

    int N = in_sizes[0] / 3;
    int E = in_sizes[1] / 3;
    float* out_node = (float*)d_out;
    float* out_edge = out_node + (size_t)N * 3;

    void* pdegi;
    cudaGetSymbolAddress(&pdegi, g_degi);
    cudaMemsetAsync(pdegi, 0, (size_t)N * sizeof(int));

    const int TB = 256;
    int gbE   = (E + TB - 1) / TB;
    int gbN   = (N + TB - 1) / TB;
    int gbN64 = (N + 63) / 64;
    int NB    = (N + 1023) / 1024;

    k_deg      <<<gbE,  TB>>>(ei, E);
    k_bsum     <<<NB, 1024>>>(N);
    k_bscan    <<<1,    32>>>(NB, N, E);
    k_rowptr   <<<NB, 1024>>>(N);
    k_scatter  <<<gbE,  TB>>>(ei, E);
    k_node1    <<<gbN,  TB>>>(x, wn1, bn1, we1, N);
    k_agg_node2<<<gbN64, TB>>>(wn2, bn2, we2, N);
    k_edge2    <<<gbE,  TB>>>(ei, ea, we1, be1, we2, be2, wen1, ben1, wen2, ben2,
                              out_edge, E);
    k_agg_node3<<<gbN64, TB>>>(wnn1, bnn1, wnn2, bnn2, out_node, N);
}

// round 6
// speedup vs baseline: 1.5584x; 1.0100x over previous
#include <cuda_runtime.h>

#define NMAX 100000
#define EMAX 3200000

typedef unsigned long long u64;

// scratch (all __device__ globals; no allocation anywhere)
__device__ int    g_degi  [NMAX];
__device__ int    g_rowptr[NMAX + 1];
__device__ int    g_next  [NMAX];
__device__ int    g_bsum  [128];
__device__ int    g_boff  [128];
__device__ int4   g_sedge [EMAX];     // (src, eid, dst, 0) sorted by dst
__device__ float  g_dis   [NMAX];
__device__ float4 g_y     [NMAX * 4]; // dis * x1hat  (layer-1 message)
__device__ float4 g_y2    [NMAX * 4]; // dis * x2hat  (layer-2 message)
__device__ float4 g_A1    [NMAX * 4];
__device__ float4 g_B1    [NMAX * 4];
__device__ float4 g_A2    [NMAX * 4];
__device__ float4 g_B2    [NMAX * 4];

__device__ __forceinline__ float relu(float v) { return fmaxf(v, 0.0f); }

__device__ __forceinline__ u64 pack2(float lo, float hi) {
    u64 r; asm("mov.b64 %0, {%1, %2};" : "=l"(r) : "f"(lo), "f"(hi)); return r;
}
__device__ __forceinline__ u64 ffma2(u64 a, u64 b, u64 c) {
    u64 d; asm("fma.rn.f32x2 %0, %1, %2, %3;" : "=l"(d) : "l"(a), "l"(b), "l"(c)); return d;
}
__device__ __forceinline__ float2 unpack2(u64 v) {
    float2 f; asm("mov.b64 {%0, %1}, %2;" : "=f"(f.x), "=f"(f.y) : "l"(v)); return f;
}

// ---------------------------------------------------------------- degree
__global__ void k_deg(const int* __restrict__ ei, int E) {
    int e = blockIdx.x * blockDim.x + threadIdx.x;
    if (e < E) atomicAdd(&g_degi[ei[(size_t)E + e]], 1);
}

// ------------------------------------- two-level scan, fully coalesced
__global__ void k_bsum(int N) {              // grid = NB, block = 1024
    int i = blockIdx.x * 1024 + threadIdx.x;
    int v = (i < N) ? g_degi[i] : 0;
#pragma unroll
    for (int o = 16; o; o >>= 1) v += __shfl_down_sync(0xFFFFFFFFu, v, o);
    __shared__ int ws[32];
    if ((threadIdx.x & 31) == 0) ws[threadIdx.x >> 5] = v;
    __syncthreads();
    if (threadIdx.x < 32) {
        int u = ws[threadIdx.x];
#pragma unroll
        for (int o = 16; o; o >>= 1) u += __shfl_down_sync(0xFFFFFFFFu, u, o);
        if (threadIdx.x == 0) g_bsum[blockIdx.x] = u;
    }
}

__global__ void k_bscan(int NB, int N, int E) {
    if (threadIdx.x == 0) {
        int run = 0;
        for (int b = 0; b < NB; b++) { g_boff[b] = run; run += g_bsum[b]; }
        g_rowptr[N] = E;
    }
}

__global__ void k_rowptr(int N) {            // grid = NB, block = 1024
    __shared__ int s[1024];
    int i = blockIdx.x * 1024 + threadIdx.x;
    int d = (i < N) ? g_degi[i] : 0;
    s[threadIdx.x] = d;
    __syncthreads();
    for (int off = 1; off < 1024; off <<= 1) {
        int u = (threadIdx.x >= off) ? s[threadIdx.x - off] : 0;
        __syncthreads();
        s[threadIdx.x] += u;
        __syncthreads();
    }
    if (i < N) {
        int excl = g_boff[blockIdx.x] + s[threadIdx.x] - d;
        g_rowptr[i] = excl;
        g_next[i]   = excl;
    }
}

// ----------------------------------------------------- scatter into CSR
__global__ void k_scatter(const int* __restrict__ ei, int E) {
    int e = blockIdx.x * blockDim.x + threadIdx.x;
    if (e >= E) return;
    int src = ei[e];
    int dst = ei[(size_t)E + e];
    int pos = atomicAdd(&g_next[dst], 1);
    g_sedge[pos] = make_int4(src, e, dst, 0);
}

// ------------------------------------------------- node precompute layer 1
__global__ void k_node1(const float* __restrict__ x,
                        const float* __restrict__ wn1, const float* __restrict__ bn1,
                        const float* __restrict__ we1, int N) {
    __shared__ float swn[48], sbn[16], sA[256], sB[256];
    for (int i = threadIdx.x; i < 48; i += blockDim.x) swn[i] = wn1[i];
    for (int i = threadIdx.x; i < 16; i += blockDim.x) sbn[i] = bn1[i];
    for (int i = threadIdx.x; i < 256; i += blockDim.x) {
        sA[i] = we1[i];            // rows 0..15  (x_src part)
        sB[i] = we1[304 + i];      // rows 19..34 (x_dst part)
    }
    __syncthreads();
    int n = blockIdx.x * blockDim.x + threadIdx.x;
    if (n >= N) return;

    float x0 = x[(size_t)n*3], x1 = x[(size_t)n*3+1], x2 = x[(size_t)n*3+2];
    float dis = rsqrtf((float)g_degi[n]);
    g_dis[n] = dis;

    float h[16];
#pragma unroll
    for (int k = 0; k < 16; k++)
        h[k] = sbn[k] + x0*swn[k] + x1*swn[16+k] + x2*swn[32+k];

    float4* Y = &g_y[(size_t)n*4];
#pragma unroll
    for (int q = 0; q < 4; q++)
        Y[q] = make_float4(dis*h[4*q], dis*h[4*q+1], dis*h[4*q+2], dis*h[4*q+3]);

    float a[16], b[16];
#pragma unroll
    for (int k = 0; k < 16; k++) { a[k] = 0.f; b[k] = 0.f; }
#pragma unroll
    for (int j = 0; j < 16; j++)
#pragma unroll
        for (int k = 0; k < 16; k++) {
            a[k] += h[j] * sA[j*16+k];
            b[k] += h[j] * sB[j*16+k];
        }
    float4* A = &g_A1[(size_t)n*4];
    float4* B = &g_B1[(size_t)n*4];
#pragma unroll
    for (int q = 0; q < 4; q++) {
        A[q] = make_float4(a[4*q], a[4*q+1], a[4*q+2], a[4*q+3]);
        B[q] = make_float4(b[4*q], b[4*q+1], b[4*q+2], b[4*q+3]);
    }
}

// ---------- fused: quad CSR-gather aggregation (layer1) + node2 transform
__global__ void k_agg_node2(const float* __restrict__ wn2, const float* __restrict__ bn2,
                            const float* __restrict__ we2, int N) {
    __shared__ float sw[256], sbn[16], sA[256], sB[256];
    __shared__ float sagg[64 * 17];
    for (int i = threadIdx.x; i < 16; i += blockDim.x) sbn[i] = bn2[i];
    for (int i = threadIdx.x; i < 256; i += blockDim.x) {
        sw[i] = wn2[i];
        sA[i] = we2[i];
        sB[i] = we2[512 + i];
    }
    __syncthreads();

    int t = threadIdx.x;
    int lane = t & 3, q = t >> 2;
    int n = blockIdx.x * 64 + q;

    float4 acc = make_float4(0.f, 0.f, 0.f, 0.f);
    if (n < N) {
        int s  = g_rowptr[n];
        int en = g_rowptr[n + 1];
#pragma unroll 4
        for (int p = s; p < en; p++) {
            int src = g_sedge[p].x;
            float4 v = g_y[(size_t)src * 4 + lane];
            acc.x += v.x; acc.y += v.y; acc.z += v.z; acc.w += v.w;
        }
    }
    float* sg = &sagg[q * 17 + lane * 4];
    sg[0] = acc.x; sg[1] = acc.y; sg[2] = acc.z; sg[3] = acc.w;
    __syncthreads();

    if (t >= 64) return;
    int n2 = blockIdx.x * 64 + t;
    if (n2 >= N) return;

    float dis = g_dis[n2];
    const float* ag = &sagg[t * 17];
    float h[16];
#pragma unroll
    for (int k = 0; k < 16; k++) h[k] = relu(dis * ag[k]);

    float v[16];
#pragma unroll
    for (int k = 0; k < 16; k++) v[k] = sbn[k];
#pragma unroll
    for (int j = 0; j < 16; j++)
#pragma unroll
        for (int k = 0; k < 16; k++) v[k] += h[j] * sw[j*16+k];

    float4* Y = &g_y2[(size_t)n2*4];
#pragma unroll
    for (int qq = 0; qq < 4; qq++)
        Y[qq] = make_float4(dis*v[4*qq], dis*v[4*qq+1], dis*v[4*qq+2], dis*v[4*qq+3]);

    float a[16], b[16];
#pragma unroll
    for (int k = 0; k < 16; k++) { a[k] = 0.f; b[k] = 0.f; }
#pragma unroll
    for (int j = 0; j < 16; j++)
#pragma unroll
        for (int k = 0; k < 16; k++) {
            a[k] += v[j] * sA[j*16+k];
            b[k] += v[j] * sB[j*16+k];
        }
    float4* A = &g_A2[(size_t)n2*4];
    float4* B = &g_B2[(size_t)n2*4];
#pragma unroll
    for (int qq = 0; qq < 4; qq++) {
        A[qq] = make_float4(a[4*qq], a[4*qq+1], a[4*qq+2], a[4*qq+3]);
        B[qq] = make_float4(b[4*qq], b[4*qq+1], b[4*qq+2], b[4*qq+3]);
    }
}

// ---------- fused: quad CSR-gather aggregation (layer2) + node output MLP
__global__ void k_agg_node3(const float* __restrict__ wnn1, const float* __restrict__ bnn1,
                            const float* __restrict__ wnn2, const float* __restrict__ bnn2,
                            float* __restrict__ out_node, int N) {
    __shared__ float sw1[256], sb1[16], sw2[48], sb2[3];
    __shared__ float sagg[64 * 17];
    for (int i = threadIdx.x; i < 256; i += blockDim.x) sw1[i] = wnn1[i];
    for (int i = threadIdx.x; i < 48;  i += blockDim.x) sw2[i] = wnn2[i];
    for (int i = threadIdx.x; i < 16;  i += blockDim.x) sb1[i] = bnn1[i];
    if (threadIdx.x < 3) sb2[threadIdx.x] = bnn2[threadIdx.x];
    __syncthreads();

    int t = threadIdx.x;
    int lane = t & 3, q = t >> 2;
    int n = blockIdx.x * 64 + q;

    float4 acc = make_float4(0.f, 0.f, 0.f, 0.f);
    if (n < N) {
        int s  = g_rowptr[n];
        int en = g_rowptr[n + 1];
#pragma unroll 4
        for (int p = s; p < en; p++) {
            int src = g_sedge[p].x;
            float4 v = g_y2[(size_t)src * 4 + lane];
            acc.x += v.x; acc.y += v.y; acc.z += v.z; acc.w += v.w;
        }
    }
    float* sg = &sagg[q * 17 + lane * 4];
    sg[0] = acc.x; sg[1] = acc.y; sg[2] = acc.z; sg[3] = acc.w;
    __syncthreads();

    if (t >= 64) return;
    int n2 = blockIdx.x * 64 + t;
    if (n2 >= N) return;

    float dis = g_dis[n2];
    const float* ag = &sagg[t * 17];
    float h[16];
#pragma unroll
    for (int k = 0; k < 16; k++) h[k] = relu(dis * ag[k]);

    float tv[16];
#pragma unroll
    for (int k = 0; k < 16; k++) tv[k] = sb1[k];
#pragma unroll
    for (int j = 0; j < 16; j++)
#pragma unroll
        for (int k = 0; k < 16; k++) tv[k] += h[j] * sw1[j*16+k];

    float o0 = sb2[0], o1 = sb2[1], o2 = sb2[2];
#pragma unroll
    for (int j = 0; j < 16; j++) {
        float tj = relu(tv[j]);
        o0 += tj * sw2[j*3    ];
        o1 += tj * sw2[j*3 + 1];
        o2 += tj * sw2[j*3 + 2];
    }
    out_node[(size_t)n2*3    ] = o0;
    out_node[(size_t)n2*3 + 1] = o1;
    out_node[(size_t)n2*3 + 2] = o2;
}

// ------- layer-2 edge kernel, CSR (dst-sorted) order + f32x2 matmuls
__global__ void k_edge2c(const float* __restrict__ ea,
                         const float* __restrict__ we1, const float* __restrict__ be1,
                         const float* __restrict__ we2, const float* __restrict__ be2,
                         const float* __restrict__ wen1, const float* __restrict__ ben1,
                         const float* __restrict__ wen2, const float* __restrict__ ben2,
                         float* __restrict__ out_edge, int E) {
    __shared__ float sm1[48], sbe1[16], sbe2[16], sb1[16], sw2[48], sb2[3];
    __shared__ __align__(16) float sm2[256];
    __shared__ __align__(16) float sw1[256];
    for (int i = threadIdx.x; i < 48; i += blockDim.x) {
        sm1[i] = we1[256 + i];     // w_e1 rows 16..18 (edge_attr part)
        sw2[i] = wen2[i];
    }
    for (int i = threadIdx.x; i < 256; i += blockDim.x) {
        sm2[i] = we2[256 + i];     // w_e2 rows 16..31 (edge part)
        sw1[i] = wen1[i];
    }
    for (int i = threadIdx.x; i < 16; i += blockDim.x) {
        sbe1[i] = be1[i]; sbe2[i] = be2[i]; sb1[i] = ben1[i];
    }
    if (threadIdx.x < 3) sb2[threadIdx.x] = ben2[threadIdx.x];
    __syncthreads();

    int p = blockIdx.x * blockDim.x + threadIdx.x;
    if (p >= E) return;
    int4 rec = g_sedge[p];
    int src = rec.x, eid = rec.y, dst = rec.z;

    float ea0 = ea[(size_t)eid*3], ea1 = ea[(size_t)eid*3+1], ea2 = ea[(size_t)eid*3+2];

    // e1 = relu(A1[src] + ea@w_mid1 + B1[dst] + b_e1)
    float e1v[16];
    {
        const float4* A = &g_A1[(size_t)src*4];
        const float4* B = &g_B1[(size_t)dst*4];
#pragma unroll
        for (int q = 0; q < 4; q++) {
            float4 ta = A[q], tb = B[q];
            float s0 = ta.x + tb.x, s1 = ta.y + tb.y, s2 = ta.z + tb.z, s3 = ta.w + tb.w;
            int k = 4*q;
            e1v[k  ] = relu(s0 + sbe1[k  ] + ea0*sm1[k  ] + ea1*sm1[16+k  ] + ea2*sm1[32+k  ]);
            e1v[k+1] = relu(s1 + sbe1[k+1] + ea0*sm1[k+1] + ea1*sm1[16+k+1] + ea2*sm1[32+k+1]);
            e1v[k+2] = relu(s2 + sbe1[k+2] + ea0*sm1[k+2] + ea1*sm1[16+k+2] + ea2*sm1[32+k+2]);
            e1v[k+3] = relu(s3 + sbe1[k+3] + ea0*sm1[k+3] + ea1*sm1[16+k+3] + ea2*sm1[32+k+3]);
        }
    }

    // e2 = relu(A2[src] + B2[dst] + be2 + e1 @ sm2)   [f32x2]
    float e2v[16];
    {
        const float4* A = &g_A2[(size_t)src*4];
        const float4* B = &g_B2[(size_t)dst*4];
        u64 acc[8];
#pragma unroll
        for (int q = 0; q < 4; q++) {
            float4 ta = A[q], tb = B[q];
            acc[2*q  ] = pack2(ta.x + tb.x + sbe2[4*q  ], ta.y + tb.y + sbe2[4*q+1]);
            acc[2*q+1] = pack2(ta.z + tb.z + sbe2[4*q+2], ta.w + tb.w + sbe2[4*q+3]);
        }
        const u64* W = (const u64*)sm2;
#pragma unroll
        for (int j = 0; j < 16; j++) {
            u64 ej = pack2(e1v[j], e1v[j]);
#pragma unroll
            for (int kk = 0; kk < 8; kk++)
                acc[kk] = ffma2(ej, W[j*8 + kk], acc[kk]);
        }
#pragma unroll
        for (int kk = 0; kk < 8; kk++) {
            float2 f = unpack2(acc[kk]);
            e2v[2*kk  ] = relu(f.x);
            e2v[2*kk+1] = relu(f.y);
        }
    }

    // t = e2 @ wen1 + b    [f32x2]
    float tvv[16];
    {
        u64 acc[8];
#pragma unroll
        for (int kk = 0; kk < 8; kk++) acc[kk] = pack2(sb1[2*kk], sb1[2*kk+1]);
        const u64* W = (const u64*)sw1;
#pragma unroll
        for (int j = 0; j < 16; j++) {
            u64 ej = pack2(e2v[j], e2v[j]);
#pragma unroll
            for (int kk = 0; kk < 8; kk++)
                acc[kk] = ffma2(ej, W[j*8 + kk], acc[kk]);
        }
#pragma unroll
        for (int kk = 0; kk < 8; kk++) {
            float2 f = unpack2(acc[kk]);
            tvv[2*kk  ] = f.x;
            tvv[2*kk+1] = f.y;
        }
    }

    float o0 = sb2[0], o1 = sb2[1], o2 = sb2[2];
#pragma unroll
    for (int j = 0; j < 16; j++) {
        float tj = relu(tvv[j]);
        o0 += tj * sw2[j*3    ];
        o1 += tj * sw2[j*3 + 1];
        o2 += tj * sw2[j*3 + 2];
    }
    out_edge[(size_t)eid*3    ] = o0;
    out_edge[(size_t)eid*3 + 1] = o1;
    out_edge[(size_t)eid*3 + 2] = o2;
}

extern "C" void kernel_launch(void* const* d_in, const int* in_sizes, int n_in,
                              void* d_out, int out_size) {
    const float* x    = (const float*)d_in[0];
    const float* ea   = (const float*)d_in[1];
    const int*   ei   = (const int*)d_in[2];      // int32 (JAX x64 disabled)
    const float *wn1 = (const float*)d_in[3],  *bn1 = (const float*)d_in[4];
    const float *we1 = (const float*)d_in[5],  *be1 = (const float*)d_in[6];
    const float *wn2 = (const float*)d_in[7],  *bn2 = (const float*)d_in[8];
    const float *we2 = (const float*)d_in[9],  *be2 = (const float*)d_in[10];
    const float *wnn1= (const float*)d_in[11], *bnn1= (const float*)d_in[12];
    const float *wnn2= (const float*)d_in[13], *bnn2= (const float*)d_in[14];
    const float *wen1= (const float*)d_in[15], *ben1= (const float*)d_in[16];
    const float *wen2= (const float*)d_in[17], *ben2= (const float*)d_in[18];

    int N = in_sizes[0] / 3;
    int E = in_sizes[1] / 3;
    float* out_node = (float*)d_out;
    float* out_edge = out_node + (size_t)N * 3;

    void* pdegi;
    cudaGetSymbolAddress(&pdegi, g_degi);
    cudaMemsetAsync(pdegi, 0, (size_t)N * sizeof(int));

    const int TB = 256;
    int gbE   = (E + TB - 1) / TB;
    int gbN   = (N + TB - 1) / TB;
    int gbN64 = (N + 63) / 64;
    int NB    = (N + 1023) / 1024;

    k_deg      <<<gbE,  TB>>>(ei, E);
    k_bsum     <<<NB, 1024>>>(N);
    k_bscan    <<<1,    32>>>(NB, N, E);
    k_rowptr   <<<NB, 1024>>>(N);
    k_scatter  <<<gbE,  TB>>>(ei, E);
    k_node1    <<<gbN,  TB>>>(x, wn1, bn1, we1, N);
    k_agg_node2<<<gbN64, TB>>>(wn2, bn2, we2, N);
    k_edge2c   <<<gbE,  TB>>>(ea, we1, be1, we2, be2, wen1, ben1, wen2, ben2,
                              out_edge, E);
    k_agg_node3<<<gbN64, TB>>>(wnn1, bnn1, wnn2, bnn2, out_node, N);
}